// round 2
// baseline (speedup 1.0000x reference)
#include <cuda_runtime.h>
#include <math.h>

#define NN 50000
#define NE 500000

// ---------------- scratch (static device globals; no allocation) ----------------
__device__ float    g_Q[(size_t)NN * 128];
__device__ float    g_K[(size_t)NN * 128];
__device__ float    g_V[(size_t)NN * 128];
__device__ float    g_score[(size_t)NE * 8];
__device__ float    g_ex[(size_t)NE * 8];
__device__ unsigned g_segmax[(size_t)NN * 8];
__device__ float    g_denom[(size_t)NN * 8];

// ---------------- helpers ----------------
__device__ __forceinline__ unsigned enc_f(float f) {
    unsigned u = __float_as_uint(f);
    return (u & 0x80000000u) ? ~u : (u | 0x80000000u);
}
__device__ __forceinline__ float dec_f(unsigned e) {
    return __uint_as_float((e & 0x80000000u) ? (e ^ 0x80000000u) : ~e);
}

// ---------------- fused GEMM (+ optional edge1 epilogue) ----------------
// C[rows,128] = A[rows,128] @ W[128,128] + bias
// 128x128 block tile, 512 threads, 4x8 per-thread microtile, packed f32x2 FMA.
// FUSED=true: instead of storing C, run the edge epilogue:
//   e_out[e] = K[src]*Q[dst]*C[e]*0.25 ; per-head score ; segmax atomics.
#define SSTR 132
#define GEMM_SMEM_BYTES (2 * 128 * SSTR * 4)

extern __shared__ float sm_f[];

template <bool FUSED>
__global__ __launch_bounds__(512, 1) void gemm_core(const float* __restrict__ A,
                                                    const float* __restrict__ W,
                                                    const float* __restrict__ bias,
                                                    float* __restrict__ Cout,
                                                    float* __restrict__ e_out,
                                                    const int* __restrict__ ei,
                                                    int rows) {
    float* Bs = sm_f;               // [128][SSTR]  W as (k, n)
    float* At = sm_f + 128 * SSTR;  // [128][SSTR]  A transposed: (k, row)
    const int tid = threadIdx.x;
    const int r0 = blockIdx.x * 128;

    // load W (16384 floats) with float4, into padded rows
    {
        const float4* W4 = (const float4*)W;
#pragma unroll
        for (int i = 0; i < 8; i++) {
            int l = tid + 512 * i;  // float4 idx 0..4095
            int k = l >> 5;
            int n4 = l & 31;
            *(float4*)(Bs + k * SSTR + n4 * 4) = W4[l];
        }
    }
    // load A tile transposed (coalesced gmem: consecutive tid -> consecutive k)
#pragma unroll
    for (int i = 0; i < 32; i++) {
        int l = tid + 512 * i;  // 0..16383
        int k = l & 127;
        int row = l >> 7;
        float v = 0.0f;
        if (r0 + row < rows) v = A[(size_t)(r0 + row) * 128 + k];
        At[k * SSTR + row] = v;
    }
    __syncthreads();

    const int tx = tid & 15;  // cols 8*tx .. 8*tx+7
    const int ty = tid >> 4;  // rows 4*ty .. 4*ty+3

    unsigned long long acc[4][4];
#pragma unroll
    for (int i = 0; i < 4; i++)
#pragma unroll
        for (int p = 0; p < 4; p++) acc[i][p] = 0ull;

    const float* ap = At + ty * 4;
    const float* bp = Bs + tx * 8;

#pragma unroll 4
    for (int k = 0; k < 128; k++) {
        float4 av = *(const float4*)(ap + k * SSTR);           // 4 A rows (warp-broadcast)
        ulonglong2 b01 = *(const ulonglong2*)(bp + k * SSTR);  // cols 0..3
        ulonglong2 b23 = *(const ulonglong2*)(bp + k * SSTR + 4);
        float a4[4] = {av.x, av.y, av.z, av.w};
#pragma unroll
        for (int i = 0; i < 4; i++) {
            unsigned ab = __float_as_uint(a4[i]);
            unsigned long long ad;
            asm("mov.b64 %0, {%1, %2};" : "=l"(ad) : "r"(ab), "r"(ab));
            asm("fma.rn.f32x2 %0, %1, %2, %0;" : "+l"(acc[i][0]) : "l"(ad), "l"(b01.x));
            asm("fma.rn.f32x2 %0, %1, %2, %0;" : "+l"(acc[i][1]) : "l"(ad), "l"(b01.y));
            asm("fma.rn.f32x2 %0, %1, %2, %0;" : "+l"(acc[i][2]) : "l"(ad), "l"(b23.x));
            asm("fma.rn.f32x2 %0, %1, %2, %0;" : "+l"(acc[i][3]) : "l"(ad), "l"(b23.y));
        }
    }

    float4 bb0 = *(const float4*)(bias + tx * 8);
    float4 bb1 = *(const float4*)(bias + tx * 8 + 4);

    if (!FUSED) {
#pragma unroll
        for (int i = 0; i < 4; i++) {
            int row = r0 + ty * 4 + i;
            if (row < rows) {
                unsigned lo, hi;
                float c[8];
#pragma unroll
                for (int p = 0; p < 4; p++) {
                    asm("mov.b64 {%0, %1}, %2;" : "=r"(lo), "=r"(hi) : "l"(acc[i][p]));
                    c[2 * p] = __uint_as_float(lo);
                    c[2 * p + 1] = __uint_as_float(hi);
                }
                float4 o0 = make_float4(c[0] + bb0.x, c[1] + bb0.y, c[2] + bb0.z, c[3] + bb0.w);
                float4 o1 = make_float4(c[4] + bb1.x, c[5] + bb1.y, c[6] + bb1.z, c[7] + bb1.w);
                *(float4*)(Cout + (size_t)row * 128 + tx * 8) = o0;
                *(float4*)(Cout + (size_t)row * 128 + tx * 8 + 4) = o1;
            }
        }
    } else {
        // stage Ee tile (+bias) into smem, then run the edge epilogue
        __syncthreads();  // done reading At/Bs
        float* Es = At;   // reuse: [128 edges][SSTR]
#pragma unroll
        for (int i = 0; i < 4; i++) {
            int row = ty * 4 + i;
            unsigned lo, hi;
            float c[8];
#pragma unroll
            for (int p = 0; p < 4; p++) {
                asm("mov.b64 {%0, %1}, %2;" : "=r"(lo), "=r"(hi) : "l"(acc[i][p]));
                c[2 * p] = __uint_as_float(lo);
                c[2 * p + 1] = __uint_as_float(hi);
            }
            float4 o0 = make_float4(c[0] + bb0.x, c[1] + bb0.y, c[2] + bb0.z, c[3] + bb0.w);
            float4 o1 = make_float4(c[4] + bb1.x, c[5] + bb1.y, c[6] + bb1.z, c[7] + bb1.w);
            *(float4*)(Es + row * SSTR + tx * 8) = o0;
            *(float4*)(Es + row * SSTR + tx * 8 + 4) = o1;
        }
        __syncthreads();

        const int wid = tid >> 5;
        const int lane = tid & 31;
        const int E = rows;
#pragma unroll
        for (int j = 0; j < 8; j++) {
            int el = wid * 8 + j;
            int e = r0 + el;
            if (e >= E) break;
            int src = __ldg(&ei[e]);
            int dst = __ldg(&ei[E + e]);
            float4 ee = *(const float4*)(Es + el * SSTR + lane * 4);
            float4 kk = *(const float4*)(g_K + (size_t)src * 128 + lane * 4);
            float4 qq = *(const float4*)(g_Q + (size_t)dst * 128 + lane * 4);
            float4 p;
            p.x = kk.x * qq.x * ee.x * 0.25f;
            p.y = kk.y * qq.y * ee.y * 0.25f;
            p.z = kk.z * qq.z * ee.z * 0.25f;
            p.w = kk.w * qq.w * ee.w * 0.25f;
            *(float4*)(e_out + (size_t)e * 128 + lane * 4) = p;

            float s = p.x + p.y + p.z + p.w;
            s += __shfl_xor_sync(0xffffffffu, s, 1);
            s += __shfl_xor_sync(0xffffffffu, s, 2);
            if ((lane & 3) == 0) {
                int h = lane >> 2;
                g_score[(size_t)e * 8 + h] = s;
                atomicMax(&g_segmax[(size_t)src * 8 + h], enc_f(s));
            }
        }
    }
}

// ---------------- init: zero h_out / denom, segmax -> 0 (encoded < all reals) ----
__global__ void init_kernel(float* __restrict__ h_out, int n_h, int n_seg) {
    int i = blockIdx.x * blockDim.x + threadIdx.x;
    if (i < n_h) h_out[i] = 0.0f;
    if (i < n_seg) {
        g_segmax[i] = 0u;
        g_denom[i] = 0.0f;
    }
}

// ---------------- edge pass 2: ex = exp(score - segmax[src]); denom += ex ---------
__global__ __launch_bounds__(256) void edge2(const int* __restrict__ ei, int E) {
    int t = blockIdx.x * blockDim.x + threadIdx.x;
    if (t >= E * 8) return;
    int e = t >> 3;
    int h = t & 7;
    int src = __ldg(&ei[e]);
    float m = dec_f(g_segmax[(size_t)src * 8 + h]);
    float ex = __expf(g_score[t] - m);
    g_ex[t] = ex;
    atomicAdd(&g_denom[(size_t)src * 8 + h], ex);
}

// ---------------- edge pass 3: h_out[src] += (ex/denom) * V[dst] ------------------
__global__ __launch_bounds__(256) void edge3(const int* __restrict__ ei,
                                             float* __restrict__ h_out, int E) {
    int gid = blockIdx.x * blockDim.x + threadIdx.x;
    int e = gid >> 5;
    int lane = gid & 31;
    if (e >= E) return;
    int src = __ldg(&ei[e]);
    int dst = __ldg(&ei[E + e]);
    int h = lane >> 2;
    float w = g_ex[(size_t)e * 8 + h] / g_denom[(size_t)src * 8 + h];
    float4 v = *(const float4*)(g_V + (size_t)dst * 128 + lane * 4);
    float* p = h_out + (size_t)src * 128 + lane * 4;
    asm volatile("red.global.add.v4.f32 [%0], {%1, %2, %3, %4};" ::"l"(p), "f"(w * v.x),
                 "f"(w * v.y), "f"(w * v.z), "f"(w * v.w)
                 : "memory");
}

// ---------------- launch ----------------
extern "C" void kernel_launch(void* const* d_in, const int* in_sizes, int n_in,
                              void* d_out, int out_size) {
    const float* x = (const float*)d_in[0];
    const float* e = (const float*)d_in[1];
    const int* ei = (const int*)d_in[2];
    const float* Wq = (const float*)d_in[3];
    const float* bq = (const float*)d_in[4];
    const float* Wk = (const float*)d_in[5];
    const float* bk = (const float*)d_in[6];
    const float* Wv = (const float*)d_in[7];
    const float* bv = (const float*)d_in[8];
    const float* We = (const float*)d_in[9];
    const float* be = (const float*)d_in[10];

    int N = in_sizes[0] / 128;
    int E = in_sizes[1] / 128;
    if (N > NN || E > NE) return;

    float* h_out = (float*)d_out;
    float* e_out = h_out + (size_t)N * 128;

    void *pQ, *pK, *pV;
    cudaGetSymbolAddress(&pQ, g_Q);
    cudaGetSymbolAddress(&pK, g_K);
    cudaGetSymbolAddress(&pV, g_V);

    cudaFuncSetAttribute(gemm_core<false>, cudaFuncAttributeMaxDynamicSharedMemorySize,
                         GEMM_SMEM_BYTES);
    cudaFuncSetAttribute(gemm_core<true>, cudaFuncAttributeMaxDynamicSharedMemorySize,
                         GEMM_SMEM_BYTES);

    int initN = N * 128;
    init_kernel<<<(initN + 255) / 256, 256>>>(h_out, initN, N * 8);

    int nb = (N + 127) / 128;
    int eb = (E + 127) / 128;
    gemm_core<false><<<nb, 512, GEMM_SMEM_BYTES>>>(x, Wq, bq, (float*)pQ, nullptr, nullptr, N);
    gemm_core<false><<<nb, 512, GEMM_SMEM_BYTES>>>(x, Wk, bk, (float*)pK, nullptr, nullptr, N);
    gemm_core<false><<<nb, 512, GEMM_SMEM_BYTES>>>(x, Wv, bv, (float*)pV, nullptr, nullptr, N);
    // fused: Ee GEMM + edge pass 1 (needs g_Q, g_K ready — stream-ordered)
    gemm_core<true><<<eb, 512, GEMM_SMEM_BYTES>>>(e, We, be, nullptr, e_out, ei, E);

    edge2<<<(E * 8 + 255) / 256, 256>>>(ei, E);
    edge3<<<((E * 32) + 255) / 256, 256>>>(ei, h_out, E);
}